// round 15
// baseline (speedup 1.0000x reference)
#include <cuda_runtime.h>
#include <cuda_bf16.h>

#define BB 2048
#define TT 128
#define NN 64
#define HH 128
#define THR 512   // 16 warps: 0-7 ATTN, 8-15 GATE
#define GRID 148  // 1 CTA/SM
#define NFULL 124 // 124 CTAs x 14 batches + 24 x 13 = 2048

typedef unsigned long long ull;

// ---------------- device scratch -----------------------------------------
__device__ __align__(16) __nv_bfloat16 g_prex_bf[(size_t)BB * NN * HH]; // [b][n][kq]
__device__ __align__(16) uint2 g_WatA[2 * 64 * 64]; // [jh][jp][kp] attn wts bf16
__device__ __align__(16) float g_W1xT[TT * HH];     // [t][k]
__device__ __align__(16) uint4 g_WhhB[64 * 128];    // [jp][q] bf16 {(i,f)j0,(g,o)j0,(i,f)j1,(g,o)j1}
__device__ __align__(16) uint4 g_WihB[32 * 128];    // [np][q]
__device__ __align__(16) float4 g_bQ[128];          // [q] bias (i,f,g,o)

__device__ __forceinline__ ull pk2(float a, float b) {
    ull r; asm("mov.b64 %0,{%1,%2};" : "=l"(r) : "f"(a), "f"(b)); return r;
}
__device__ __forceinline__ void fma2(ull& d, ull a, ull b) {
    asm("fma.rn.f32x2 %0, %1, %2, %0;" : "+l"(d) : "l"(a), "l"(b));
}
__device__ __forceinline__ float2 up2(ull v) {
    float2 r; asm("mov.b64 {%0,%1},%2;" : "=f"(r.x), "=f"(r.y) : "l"(v)); return r;
}
__device__ __forceinline__ ull expw(unsigned wd) {   // bf16x2 -> f32x2
    unsigned lo = wd << 16, hi = wd & 0xFFFF0000u;
    ull r; asm("mov.b64 %0,{%1,%2};" : "=l"(r) : "r"(lo), "r"(hi)); return r;
}
__device__ __forceinline__ float tanh_fast(float x) {
    float y; asm("tanh.approx.f32 %0, %1;" : "=f"(y) : "f"(x)); return y;
}
__device__ __forceinline__ float sigmoid_f(float x) {
    return 1.0f / (1.0f + __expf(-x));
}
__device__ __forceinline__ void fma4(float4& a, float s, const float4 w) {
    a.x = fmaf(s, w.x, a.x); a.y = fmaf(s, w.y, a.y);
    a.z = fmaf(s, w.z, a.z); a.w = fmaf(s, w.w, a.w);
}
__device__ __forceinline__ unsigned b2u(__nv_bfloat162 v) {
    unsigned r; *(__nv_bfloat162*)&r = v; return r;
}

// ---------------- kernel 0: weight layout prep ----------------------------
__global__ void prep_kernel(const float* __restrict__ W_attn1,
                            const float* __restrict__ W_ih,
                            const float* __restrict__ W_hh,
                            const float* __restrict__ b_ih,
                            const float* __restrict__ b_hh)
{
    int tid = blockIdx.x * blockDim.x + threadIdx.x;
    int nt  = gridDim.x * blockDim.x;
    // attn: Wt[j][k] = W_attn1[k*384 + j]; jh0 -> j<128 (h), jh1 -> j>=128 (c)
    for (int i = tid; i < 2 * 64 * 64; i += nt) {
        int jh = i >> 12, jp = (i >> 6) & 63, kp = i & 63;
        int j0 = jh * 128 + jp * 2, j1 = j0 + 1;
        int k0 = kp * 2, k1 = k0 + 1;
        uint2 v;
        v.x = b2u(__floats2bfloat162_rn(W_attn1[k0*384 + j0], W_attn1[k1*384 + j0]));
        v.y = b2u(__floats2bfloat162_rn(W_attn1[k0*384 + j1], W_attn1[k1*384 + j1]));
        g_WatA[i] = v;
    }
    for (int i = tid; i < TT * HH; i += nt) {
        int t = i >> 7, k = i & 127;
        g_W1xT[i] = W_attn1[k * 384 + 256 + t];
    }
    for (int i = tid; i < 64 * 128; i += nt) {
        int jp = i >> 7, q = i & 127;
        int j0 = jp * 2, j1 = j0 + 1;
        uint4 v;
        v.x = b2u(__floats2bfloat162_rn(W_hh[(0*HH+q)*HH + j0], W_hh[(1*HH+q)*HH + j0]));
        v.y = b2u(__floats2bfloat162_rn(W_hh[(2*HH+q)*HH + j0], W_hh[(3*HH+q)*HH + j0]));
        v.z = b2u(__floats2bfloat162_rn(W_hh[(0*HH+q)*HH + j1], W_hh[(1*HH+q)*HH + j1]));
        v.w = b2u(__floats2bfloat162_rn(W_hh[(2*HH+q)*HH + j1], W_hh[(3*HH+q)*HH + j1]));
        g_WhhB[i] = v;
    }
    for (int i = tid; i < 32 * 128; i += nt) {
        int np = i >> 7, q = i & 127;
        int n0 = np * 2, n1 = n0 + 1;
        uint4 v;
        v.x = b2u(__floats2bfloat162_rn(W_ih[(0*HH+q)*NN + n0], W_ih[(1*HH+q)*NN + n0]));
        v.y = b2u(__floats2bfloat162_rn(W_ih[(2*HH+q)*NN + n0], W_ih[(3*HH+q)*NN + n0]));
        v.z = b2u(__floats2bfloat162_rn(W_ih[(0*HH+q)*NN + n1], W_ih[(1*HH+q)*NN + n1]));
        v.w = b2u(__floats2bfloat162_rn(W_ih[(2*HH+q)*NN + n1], W_ih[(3*HH+q)*NN + n1]));
        g_WihB[i] = v;
    }
    for (int i = tid; i < 128; i += nt) {
        float4 v;
        v.x = b_ih[0*HH + i] + b_hh[0*HH + i];
        v.y = b_ih[1*HH + i] + b_hh[1*HH + i];
        v.z = b_ih[2*HH + i] + b_hh[2*HH + i];
        v.w = b_ih[3*HH + i] + b_hh[3*HH + i];
        g_bQ[i] = v;
    }
}

// ---------------- kernel 1: pre_x (bf16 out) ------------------------------
__global__ __launch_bounds__(256) void prex_kernel(const float* __restrict__ X,
                                                   const float* __restrict__ b_attn1)
{
    __shared__ float sX[TT * NN];
    int b = blockIdx.x;
    int tid = threadIdx.x;
    const float* Xb = X + (size_t)b * TT * NN;
    for (int i = tid; i < TT * NN; i += 256) sX[i] = Xb[i];
    __syncthreads();

    const float4* W4  = (const float4*)g_W1xT;
    const float4* b14 = (const float4*)b_attn1;
    uint2* out2 = (uint2*)(g_prex_bf + (size_t)b * NN * HH);

    for (int qi = tid; qi < NN * 32; qi += 256) {
        int n = qi >> 5, kq = qi & 31;
        float4 acc = b14[kq];
        #pragma unroll 4
        for (int t = 0; t < TT; ++t) {
            float x = sX[t * NN + n];
            fma4(acc, x, W4[t * 32 + kq]);
        }
        uint2 st;
        st.x = b2u(__floats2bfloat162_rn(acc.x, acc.y));
        st.y = b2u(__floats2bfloat162_rn(acc.z, acc.w));
        out2[n * 32 + kq] = st;
    }
}

// dummy: aligns ncu -s 5 -c 1 onto rnn_kernel
__global__ void dummy_kernel() {}

// ---------------- attention tanh/softmax for one batch --------------------
__device__ __forceinline__ void attn_tanh(
    int m, int l, int kqd, const ull* sUpp, const uint2* prb, const float* Xr,
    float4 wA, float4 wB, float4 wC, float4 wD, float b2, ull* xw)
{
    // u quads = jh0 + jh1 partials (sUpp: [jh][14 b][64 kp] ull)
    const ulonglong2* u0p = (const ulonglong2*)(sUpp + (size_t)m * 64);
    const ulonglong2* u1p = (const ulonglong2*)(sUpp + (size_t)(14 + m) * 64);
    float4 u0, u1, u2, u3;
    {
        ulonglong2 a = u0p[kqd], c = u1p[kqd];
        float2 ax = up2(a.x), ay = up2(a.y), cx = up2(c.x), cy = up2(c.y);
        u0 = make_float4(ax.x + cx.x, ax.y + cx.y, ay.x + cy.x, ay.y + cy.y);
        a = u0p[kqd + 8];  c = u1p[kqd + 8];
        ax = up2(a.x); ay = up2(a.y); cx = up2(c.x); cy = up2(c.y);
        u1 = make_float4(ax.x + cx.x, ax.y + cx.y, ay.x + cy.x, ay.y + cy.y);
        a = u0p[kqd + 16]; c = u1p[kqd + 16];
        ax = up2(a.x); ay = up2(a.y); cx = up2(c.x); cy = up2(c.y);
        u2 = make_float4(ax.x + cx.x, ax.y + cx.y, ay.x + cy.x, ay.y + cy.y);
        a = u0p[kqd + 24]; c = u1p[kqd + 24];
        ax = up2(a.x); ay = up2(a.y); cx = up2(c.x); cy = up2(c.y);
        u3 = make_float4(ax.x + cx.x, ax.y + cx.y, ay.x + cy.x, ay.y + cy.y);
    }
    float ee[2];
    #pragma unroll
    for (int p = 0; p < 2; ++p) {
        int nb = p * 32 + (l & 24);
        const uint2* pp = prb + (size_t)nb * 32 + kqd;
        uint2 c0 = __ldcs(pp), c1 = __ldcs(pp + 8);
        uint2 c2 = __ldcs(pp + 16), c3 = __ldcs(pp + 24);
        float v[8];
        #pragma unroll
        for (int i = 0; i < 8; ++i) {
            const uint2* pn = prb + (size_t)(nb + ((i + 1) & 7)) * 32 + kqd;
            uint2 n0 = __ldcs(pn), n1 = __ldcs(pn + 8);
            uint2 n2 = __ldcs(pn + 16), n3 = __ldcs(pn + 24);
            float s;
            {
                float2 a01 = __bfloat1622float2(*(const __nv_bfloat162*)&c0.x);
                float2 a23 = __bfloat1622float2(*(const __nv_bfloat162*)&c0.y);
                s = tanh_fast(a01.x + u0.x) * wA.x;
                s = fmaf(tanh_fast(a01.y + u0.y), wA.y, s);
                s = fmaf(tanh_fast(a23.x + u0.z), wA.z, s);
                s = fmaf(tanh_fast(a23.y + u0.w), wA.w, s);
            }
            {
                float2 a01 = __bfloat1622float2(*(const __nv_bfloat162*)&c1.x);
                float2 a23 = __bfloat1622float2(*(const __nv_bfloat162*)&c1.y);
                s = fmaf(tanh_fast(a01.x + u1.x), wB.x, s);
                s = fmaf(tanh_fast(a01.y + u1.y), wB.y, s);
                s = fmaf(tanh_fast(a23.x + u1.z), wB.z, s);
                s = fmaf(tanh_fast(a23.y + u1.w), wB.w, s);
            }
            {
                float2 a01 = __bfloat1622float2(*(const __nv_bfloat162*)&c2.x);
                float2 a23 = __bfloat1622float2(*(const __nv_bfloat162*)&c2.y);
                s = fmaf(tanh_fast(a01.x + u2.x), wC.x, s);
                s = fmaf(tanh_fast(a01.y + u2.y), wC.y, s);
                s = fmaf(tanh_fast(a23.x + u2.z), wC.z, s);
                s = fmaf(tanh_fast(a23.y + u2.w), wC.w, s);
            }
            {
                float2 a01 = __bfloat1622float2(*(const __nv_bfloat162*)&c3.x);
                float2 a23 = __bfloat1622float2(*(const __nv_bfloat162*)&c3.y);
                s = fmaf(tanh_fast(a01.x + u3.x), wD.x, s);
                s = fmaf(tanh_fast(a01.y + u3.y), wD.y, s);
                s = fmaf(tanh_fast(a23.x + u3.z), wD.z, s);
                s = fmaf(tanh_fast(a23.y + u3.w), wD.w, s);
            }
            v[i] = s;
            c0 = n0; c1 = n1; c2 = n2; c3 = n3;
        }
        bool h1 = l & 1, h2 = l & 2, h4 = l & 4;
        float s0 = h1 ? v[0] : v[1];
        float a0 = (h1 ? v[1] : v[0]) + __shfl_xor_sync(0xffffffffu, s0, 1);
        float s1 = h1 ? v[2] : v[3];
        float a1 = (h1 ? v[3] : v[2]) + __shfl_xor_sync(0xffffffffu, s1, 1);
        float s2 = h1 ? v[4] : v[5];
        float a2 = (h1 ? v[5] : v[4]) + __shfl_xor_sync(0xffffffffu, s2, 1);
        float s3 = h1 ? v[6] : v[7];
        float a3 = (h1 ? v[7] : v[6]) + __shfl_xor_sync(0xffffffffu, s3, 1);
        float t0 = h2 ? a0 : a1;
        float bb0 = (h2 ? a1 : a0) + __shfl_xor_sync(0xffffffffu, t0, 2);
        float t1 = h2 ? a2 : a3;
        float bb1 = (h2 ? a3 : a2) + __shfl_xor_sync(0xffffffffu, t1, 2);
        float t2 = h4 ? bb0 : bb1;
        float ev = (h4 ? bb1 : bb0) + __shfl_xor_sync(0xffffffffu, t2, 4);
        ee[p] = ev + b2;
    }
    float e0 = ee[0], e1 = ee[1];
    float mx = fmaxf(e0, e1);
    #pragma unroll
    for (int o = 16; o > 0; o >>= 1)
        mx = fmaxf(mx, __shfl_xor_sync(0xffffffffu, mx, o));
    float x0 = __expf(e0 - mx), x1 = __expf(e1 - mx);
    float sm = x0 + x1;
    #pragma unroll
    for (int o = 16; o > 0; o >>= 1)
        sm += __shfl_xor_sync(0xffffffffu, sm, o);
    float inv = 1.0f / sm;
    float xv0 = x0 * inv * Xr[l];
    float xv1 = x1 * inv * Xr[l + 32];
    xw[((l >> 1) * 14 + m) * 2 + (l & 1)]        = pk2(xv0, xv0);
    xw[(((l >> 1) + 16) * 14 + m) * 2 + (l & 1)] = pk2(xv1, xv1);
}

// ---------------- kernel 2: smem-resident warp-specialized recurrence -----
// dyn smem bytes: sWhh 131072 | hd 14336 | cd 14336 | sUpp 14336 | xwd 7168
#define SM_BYTES 181248

__global__ __launch_bounds__(THR, 1) void rnn_kernel(
    const float* __restrict__ X,
    const float* __restrict__ w_attn2,
    const float* __restrict__ b_attn2,
    float* __restrict__ out)
{
    extern __shared__ __align__(16) unsigned char sm[];
    uint4*      sWhh = (uint4*)sm;                  // [64 jp][128 q]
    ulonglong2* hd   = (ulonglong2*)(sm + 131072);  // [64 jp][14 b] h dup
    ulonglong2* cd   = (ulonglong2*)(sm + 145408);  // [64 jp][14 b] c dup
    ull*        sUpp = (ull*)(sm + 159744);         // [2 jh][14 b][64 kp]
    ull*        xwd  = (ull*)(sm + 174080);         // [32 np][14 b] x dup

    int tid = threadIdx.x, l = tid & 31, w = tid >> 5;
    int cta = blockIdx.x;
    int cnt = (cta < NFULL) ? 14 : 13;
    size_t b0 = (cta < NFULL) ? (size_t)cta * 14
                              : (size_t)(NFULL * 14 + (cta - NFULL) * 13);

    {   // stage Whh bf16 into smem (once, reused 128 steps); zero state
        const uint4* src = (const uint4*)g_WhhB;
        uint4* dst = sWhh;
        #pragma unroll 4
        for (int i = tid; i < 8192; i += THR) dst[i] = src[i];
        ull* z = (ull*)(sm + 131072);
        for (int i = tid; i < 6272; i += THR) z[i] = 0ull;
    }
    __syncthreads();

    if (w < 8) {
        // ================= ATTN warps (threads 0-255) =================
        int kp = tid & 63, jh = (tid >> 6) & 1, grp = tid >> 7;
        int bb = grp * 7;
        const uint2* Wat = g_WatA + (size_t)jh * 4096 + kp;   // [jp][64]
        const ulonglong2* hx = jh ? cd : hd;
        float b2 = b_attn2[0];
        int kqd = l & 7;
        const float4* w24 = (const float4*)w_attn2;
        float4 wA = w24[kqd], wB = w24[kqd + 8], wC = w24[kqd + 16], wD = w24[kqd + 24];
        int m0 = w, m1 = w + 8;
        int c1 = (m1 < cnt) ? m1 : (cnt - 1);
        const uint2* pr0 = (const uint2*)g_prex_bf + (size_t)(b0 + m0) * 2048;
        const uint2* pr1 = (const uint2*)g_prex_bf + (size_t)(b0 + c1) * 2048;
        const float* X0 = X + (size_t)(b0 + m0) * TT * NN;
        const float* X1 = X + (size_t)(b0 + c1) * TT * NN;
        ull* su = sUpp + (size_t)(jh * 14 + bb) * 64 + kp;

        for (int t = 0; t < TT; ++t) {
            // u partials over this jh-half's 128 j for 7 batches
            ull a0 = 0, a1 = 0, a2 = 0, a3 = 0, a4 = 0, a5 = 0, a6 = 0;
            #pragma unroll 4
            for (int jp = 0; jp < 64; ++jp) {
                uint2 wd = Wat[jp * 64];
                ull w0 = expw(wd.x), w1 = expw(wd.y);
                const ulonglong2* hb = hx + jp * 14 + bb;
                ulonglong2 p0 = hb[0], p1 = hb[1], p2 = hb[2], p3 = hb[3];
                ulonglong2 p4 = hb[4], p5 = hb[5], p6 = hb[6];
                fma2(a0, p0.x, w0); fma2(a0, p0.y, w1);
                fma2(a1, p1.x, w0); fma2(a1, p1.y, w1);
                fma2(a2, p2.x, w0); fma2(a2, p2.y, w1);
                fma2(a3, p3.x, w0); fma2(a3, p3.y, w1);
                fma2(a4, p4.x, w0); fma2(a4, p4.y, w1);
                fma2(a5, p5.x, w0); fma2(a5, p5.y, w1);
                fma2(a6, p6.x, w0); fma2(a6, p6.y, w1);
            }
            su[0*64] = a0; su[1*64] = a1; su[2*64] = a2; su[3*64] = a3;
            su[4*64] = a4; su[5*64] = a5; su[6*64] = a6;
            asm volatile("bar.sync 3, 256;" ::: "memory");   // u partials ready

            attn_tanh(m0, l, kqd, sUpp, pr0, X0 + (size_t)t * NN,
                      wA, wB, wC, wD, b2, xwd);
            if (m1 < cnt)
                attn_tanh(m1, l, kqd, sUpp, pr1, X1 + (size_t)t * NN,
                          wA, wB, wC, wD, b2, xwd);

            asm volatile("bar.sync 1, 512;" ::: "memory");   // x~ ready
            asm volatile("bar.sync 2, 512;" ::: "memory");   // h/c updated
        }
    } else {
        // ================= GATE warps (threads 256-511) =================
        int q = tid & 127, grp = (tid >> 7) & 1;
        int bb = grp * 7;
        const uint4* Wq  = sWhh + q;                  // [jp][128]
        const uint4* WiQ = g_WihB + q;                // [np][128] (L2)
        float4 bq = g_bQ[q];
        ull bIF = pk2(bq.x, bq.y), bGO = pk2(bq.z, bq.w);
        float cr[7];
        #pragma unroll
        for (int b = 0; b < 7; ++b) cr[b] = 0.0f;
        ull* hw = (ull*)hd;
        ull* cw = (ull*)cd;
        int hbase = ((q >> 1) * 14) * 2 + (q & 1);

        for (int t = 0; t < TT; ++t) {
            ull aIF[7], aGO[7];
            #pragma unroll
            for (int b = 0; b < 7; ++b) { aIF[b] = bIF; aGO[b] = bGO; }
            // Whh . h  (smem-resident weights; overlaps ATTN u/tanh/softmax)
            #pragma unroll 4
            for (int jp = 0; jp < 64; ++jp) {
                uint4 wt = Wq[jp * 128];
                ull wIF0 = expw(wt.x), wGO0 = expw(wt.y);
                ull wIF1 = expw(wt.z), wGO1 = expw(wt.w);
                const ulonglong2* hb = hd + jp * 14 + bb;
                #pragma unroll
                for (int b = 0; b < 7; ++b) {
                    ulonglong2 p = hb[b];
                    fma2(aIF[b], p.x, wIF0); fma2(aGO[b], p.x, wGO0);
                    fma2(aIF[b], p.y, wIF1); fma2(aGO[b], p.y, wGO1);
                }
            }
            asm volatile("bar.sync 1, 512;" ::: "memory");   // wait x~
            // Wih . x~  (bf16 from L2, 32 coalesced LDG.128)
            #pragma unroll 4
            for (int np = 0; np < 32; ++np) {
                uint4 wt = WiQ[np * 128];
                ull wIF0 = expw(wt.x), wGO0 = expw(wt.y);
                ull wIF1 = expw(wt.z), wGO1 = expw(wt.w);
                const ulonglong2* xb = (const ulonglong2*)xwd + np * 14 + bb;
                #pragma unroll
                for (int b = 0; b < 7; ++b) {
                    ulonglong2 p = xb[b];
                    fma2(aIF[b], p.x, wIF0); fma2(aGO[b], p.x, wGO0);
                    fma2(aIF[b], p.y, wIF1); fma2(aGO[b], p.y, wGO1);
                }
            }
            // pointwise LSTM update (thread owns all 4 gates of q)
            #pragma unroll
            for (int b = 0; b < 7; ++b) {
                int gb = bb + b;
                float2 rIF = up2(aIF[b]), rGO = up2(aGO[b]);
                float iv = sigmoid_f(rIF.x);
                float fv = sigmoid_f(rIF.y);
                float gv = tanhf(rGO.x);
                float ov = sigmoid_f(rGO.y);
                float c2 = fv * cr[b] + iv * gv;
                cr[b] = c2;
                float hn = ov * tanhf(c2);
                if (gb < cnt) {
                    hw[hbase + gb * 2] = pk2(hn, hn);
                    cw[hbase + gb * 2] = pk2(c2, c2);
                    out[((size_t)(b0 + gb) * TT + t) * HH + q] = hn;
                }
            }
            asm volatile("bar.sync 2, 512;" ::: "memory");   // h/c published
        }
    }
}

// ---------------- launch --------------------------------------------------
extern "C" void kernel_launch(void* const* d_in, const int* in_sizes, int n_in,
                              void* d_out, int out_size) {
    const float* X       = (const float*)d_in[0];
    const float* W_attn1 = (const float*)d_in[1];
    const float* b_attn1 = (const float*)d_in[2];
    const float* w_attn2 = (const float*)d_in[3];
    const float* b_attn2 = (const float*)d_in[4];
    const float* W_ih    = (const float*)d_in[5];
    const float* W_hh    = (const float*)d_in[6];
    const float* b_ih    = (const float*)d_in[7];
    const float* b_hh    = (const float*)d_in[8];
    float* out = (float*)d_out;

    cudaFuncSetAttribute(rnn_kernel, cudaFuncAttributeMaxDynamicSharedMemorySize,
                         SM_BYTES);

    prep_kernel<<<64, 256>>>(W_attn1, W_ih, W_hh, b_ih, b_hh);
    prex_kernel<<<BB, 256>>>(X, b_attn1);
    dummy_kernel<<<1, 32>>>();   // aligns ncu -s 5 -c 1 onto rnn_kernel
    rnn_kernel<<<GRID, THR, SM_BYTES>>>(X, w_attn2, b_attn2, out);
}

// round 16
// speedup vs baseline: 1.1592x; 1.1592x over previous
#include <cuda_runtime.h>
#include <cuda_bf16.h>

#define BB 2048
#define TT 128
#define NN 64
#define HH 128
#define THR 256   // threads per CTA (8 warps)
#define GRID 296  // 2 CTAs per SM
#define NFULL 272 // CTAs with 7 batches; remaining 24 have 6
#define HCP 264   // padded hc row stride (floats)
#define SUP 132   // padded sU row stride (floats)

typedef unsigned long long ull;

// ---------------- device scratch (allocation-free: __device__ globals) -------
__device__ __align__(16) __nv_bfloat16 g_prex_bf[(size_t)BB * NN * HH]; // [b][n][kq]
__device__ __align__(16) uint2 g_WatB[256 * 32];   // [j][kq] bf16x4 attention wts
__device__ __align__(16) float g_W1xT[TT * HH];    // [t][k]
__device__ __align__(16) uint2 g_WhhB[HH * 128];   // [j][q] bf16x2 pair {(i,f),(g,o)}
__device__ __align__(16) uint2 g_WihB[NN * 128];   // [n][q]
__device__ __align__(16) float g_bG[512];          // [q*4+gate] fp32

__device__ __forceinline__ ull pk2(float a, float b) {
    ull r; asm("mov.b64 %0,{%1,%2};" : "=l"(r) : "f"(a), "f"(b)); return r;
}
__device__ __forceinline__ void fma2(ull& d, ull a, ull b) {
    asm("fma.rn.f32x2 %0, %1, %2, %0;" : "+l"(d) : "l"(a), "l"(b));
}
__device__ __forceinline__ float2 up2(ull v) {
    float2 r; asm("mov.b64 {%0,%1},%2;" : "=f"(r.x), "=f"(r.y) : "l"(v)); return r;
}
// bf16x2 word -> packed f32x2 (low bf16 -> low f32)
__device__ __forceinline__ ull expw(unsigned wd) {
    unsigned lo = wd << 16, hi = wd & 0xFFFF0000u;
    ull r; asm("mov.b64 %0,{%1,%2};" : "=l"(r) : "r"(lo), "r"(hi)); return r;
}
__device__ __forceinline__ float tanh_fast(float x) {
    float y; asm("tanh.approx.f32 %0, %1;" : "=f"(y) : "f"(x)); return y;
}
__device__ __forceinline__ float sigmoid_f(float x) {
    return 1.0f / (1.0f + __expf(-x));
}
__device__ __forceinline__ void fma4(float4& a, float s, const float4 w) {
    a.x = fmaf(s, w.x, a.x); a.y = fmaf(s, w.y, a.y);
    a.z = fmaf(s, w.z, a.z); a.w = fmaf(s, w.w, a.w);
}
__device__ __forceinline__ unsigned b2u(__nv_bfloat162 v) {
    unsigned r; *(__nv_bfloat162*)&r = v; return r;
}

// ---------------- kernel 0: weight layout prep --------------------------------
__global__ void prep_kernel(const float* __restrict__ W_attn1,
                            const float* __restrict__ W_ih,
                            const float* __restrict__ W_hh,
                            const float* __restrict__ b_ih,
                            const float* __restrict__ b_hh)
{
    int tid = blockIdx.x * blockDim.x + threadIdx.x;
    int nt  = gridDim.x * blockDim.x;
    // attention weights bf16: WatB[j][kq] = {bf16x2(k0,k1), bf16x2(k2,k3)},
    // W^T[j][k] = W_attn1[k*384 + j] (j<128: W1_h col; j>=128: W1_s col)
    for (int i = tid; i < 256 * 32; i += nt) {
        int j = i >> 5, kq = i & 31, k = kq * 4;
        uint2 v;
        v.x = b2u(__floats2bfloat162_rn(W_attn1[(k+0)*384 + j], W_attn1[(k+1)*384 + j]));
        v.y = b2u(__floats2bfloat162_rn(W_attn1[(k+2)*384 + j], W_attn1[(k+3)*384 + j]));
        g_WatB[i] = v;
    }
    for (int i = tid; i < TT * HH; i += nt) {
        int t = i >> 7, k = i & 127;
        g_W1xT[i] = W_attn1[k * 384 + 256 + t];
    }
    // gate weights bf16: [j][q] = {(i,f) pair, (g,o) pair}
    for (int i = tid; i < HH * 128; i += nt) {
        int j = i >> 7, q = i & 127;
        uint2 v;
        v.x = b2u(__floats2bfloat162_rn(W_hh[(0*HH+q)*HH + j], W_hh[(1*HH+q)*HH + j]));
        v.y = b2u(__floats2bfloat162_rn(W_hh[(2*HH+q)*HH + j], W_hh[(3*HH+q)*HH + j]));
        g_WhhB[i] = v;
    }
    for (int i = tid; i < NN * 128; i += nt) {
        int n = i >> 7, q = i & 127;
        uint2 v;
        v.x = b2u(__floats2bfloat162_rn(W_ih[(0*HH+q)*NN + n], W_ih[(1*HH+q)*NN + n]));
        v.y = b2u(__floats2bfloat162_rn(W_ih[(2*HH+q)*NN + n], W_ih[(3*HH+q)*NN + n]));
        g_WihB[i] = v;
    }
    for (int i = tid; i < 512; i += nt) {
        int q = i >> 2, g = i & 3;
        g_bG[i] = b_ih[g * HH + q] + b_hh[g * HH + q];
    }
}

// ---------------- kernel 1: pre_x (bf16 out) ----------------------------------
__global__ __launch_bounds__(256) void prex_kernel(const float* __restrict__ X,
                                                   const float* __restrict__ b_attn1)
{
    __shared__ float sX[TT * NN];
    int b = blockIdx.x;
    int tid = threadIdx.x;
    const float* Xb = X + (size_t)b * TT * NN;
    for (int i = tid; i < TT * NN; i += 256) sX[i] = Xb[i];
    __syncthreads();

    const float4* W4  = (const float4*)g_W1xT;
    const float4* b14 = (const float4*)b_attn1;
    uint2* out2 = (uint2*)(g_prex_bf + (size_t)b * NN * HH);

    for (int qi = tid; qi < NN * 32; qi += 256) {
        int n = qi >> 5, kq = qi & 31;
        float4 acc = b14[kq];
        #pragma unroll 4
        for (int t = 0; t < TT; ++t) {
            float x = sX[t * NN + n];
            fma4(acc, x, W4[t * 32 + kq]);
        }
        uint2 st;
        st.x = b2u(__floats2bfloat162_rn(acc.x, acc.y));
        st.y = b2u(__floats2bfloat162_rn(acc.z, acc.w));
        out2[n * 32 + kq] = st;
    }
}

// dummy: shifts launch numbering so ncu (-s 5 -c 1) lands on rnn_kernel
__global__ void dummy_kernel() {}

// ---------------- kernel 2: the recurrence ------------------------------------
// smem (floats): sWb 16384 (bf16 attn wts) | hcA 2112 | hcB 2112 | sU 1056 | sXT 512
#define SMEM_FLOATS (16384 + 2112 + 2112 + 1056 + 512)

#define PKS(c) p0 = pk2(v0.c, v0.c); p1 = pk2(v1.c, v1.c); \
               p2 = pk2(v2.c, v2.c); p3 = pk2(v3.c, v3.c)
#define GSTEP(wl, wh) { ull wx = expw(wl), wy = expw(wh); \
    fma2(aL0, p0, wx); fma2(aH0, p0, wy); fma2(aL1, p1, wx); fma2(aH1, p1, wy); \
    fma2(aL2, p2, wx); fma2(aH2, p2, wy); fma2(aL3, p3, wx); fma2(aH3, p3, wy); }

__global__ __launch_bounds__(THR, 2) void rnn_kernel(
    const float* __restrict__ X,
    const float* __restrict__ w_attn2,
    const float* __restrict__ b_attn2,
    float* __restrict__ out)
{
    extern __shared__ float smem[];
    uint2* sWb = (uint2*)smem;            // [256][32]
    float* hcA = smem + 16384;
    float* hcB = hcA + 2112;
    float* sU  = hcB + 2112;
    float* sXT = sU + 1056;

    int tid = threadIdx.x;
    int l = tid & 31;
    int w = tid >> 5;                      // 0..7
    int cta = blockIdx.x;
    int cnt  = (cta < NFULL) ? 7 : 6;
    size_t b0 = (cta < NFULL) ? (size_t)cta * 7
                              : (size_t)(NFULL * 7 + (cta - NFULL) * 6);

    {   // stage bf16 attention weights into smem (once)
        const uint4* src = (const uint4*)g_WatB;
        uint4* dst = (uint4*)sWb;
        #pragma unroll 4
        for (int i = tid; i < 4096; i += THR) dst[i] = src[i];
    }
    for (int i = tid; i < 4224; i += THR) hcA[i] = 0.0f;   // zero both hc buffers
    for (int i = tid; i < 512; i += THR) sXT[i] = 0.0f;

    float b2 = b_attn2[0];

    // (a) mapping: warp w -> batch-group (w>>2: 4 batches), k-group (w&3: 32 k)
    int mA  = (w >> 2) * 4 + (l >> 3);     // 0..7
    int kqA = (w & 3) * 8 + (l & 7);       // k-quad 0..31

    // (d) mapping: q in 0..127, 2 groups of 4 batches
    int q = tid & 127, grp = tid >> 7, mb = grp * 4;
    float4 bgq = ((const float4*)g_bG)[q];
    ull bLo = pk2(bgq.x, bgq.y), bHi = pk2(bgq.z, bgq.w);

    int mw = (w < cnt) ? w : 0;
    const uint2* prb = (const uint2*)g_prex_bf + (size_t)(b0 + mw) * 2048;

    __syncthreads();

    for (int t = 0; t < TT; ++t) {
        float* hc  = (t & 1) ? hcB : hcA;
        float* hcn = (t & 1) ? hcA : hcB;

        // ---- (a) u[m][k] = sum_j [h|c][m][j] * WatT[j][k]  (bf16 smem wts)
        {
            const float4* hcm4 = (const float4*)(hc + mA * HCP);
            ull a0 = 0ull, a1 = 0ull;
            #pragma unroll 4
            for (int j4 = 0; j4 < 64; ++j4) {
                float4 hv = hcm4[j4];
                uint2 w0 = sWb[(j4 * 4 + 0) * 32 + kqA];
                uint2 w1 = sWb[(j4 * 4 + 1) * 32 + kqA];
                uint2 w2 = sWb[(j4 * 4 + 2) * 32 + kqA];
                uint2 w3 = sWb[(j4 * 4 + 3) * 32 + kqA];
                ull p0 = pk2(hv.x, hv.x), p1 = pk2(hv.y, hv.y);
                ull p2 = pk2(hv.z, hv.z), p3 = pk2(hv.w, hv.w);
                fma2(a0, p0, expw(w0.x)); fma2(a1, p0, expw(w0.y));
                fma2(a0, p1, expw(w1.x)); fma2(a1, p1, expw(w1.y));
                fma2(a0, p2, expw(w2.x)); fma2(a1, p2, expw(w2.y));
                fma2(a0, p3, expw(w3.x)); fma2(a1, p3, expw(w3.y));
            }
            float2 r0 = up2(a0), r1 = up2(a1);
            ((float4*)(sU + mA * SUP))[kqA] = make_float4(r0.x, r0.y, r1.x, r1.y);
        }
        __syncthreads();

        // ---- (b)+(c): e, softmax, x_tilde. warp=m; lane ends with e[n=l].
        //      pre_x via PLAIN loads: the only cross-step-reused stream gets to
        //      live in L1 (weights are streamed bf16 and no longer thrash it).
        if (w < cnt) {
            int kq = l & 7;
            const float4* sUr = (const float4*)(sU + w * SUP);
            float4 u0 = sUr[kq], u1 = sUr[kq + 8], u2 = sUr[kq + 16], u3 = sUr[kq + 24];
            const float4* w24 = (const float4*)w_attn2;
            float4 wA = w24[kq], wB = w24[kq + 8], wC = w24[kq + 16], wD = w24[kq + 24];
            float ee[2];
            #pragma unroll
            for (int p = 0; p < 2; ++p) {
                int nb = p * 32 + (l & 24);
                const uint2* pp = prb + (size_t)nb * 32 + kq;
                uint2 c0 = pp[0], c1 = pp[8], c2 = pp[16], c3 = pp[24];
                float v[8];
                #pragma unroll
                for (int i = 0; i < 8; ++i) {
                    const uint2* pn = prb + (size_t)(nb + ((i + 1) & 7)) * 32 + kq;
                    uint2 n0 = pn[0], n1 = pn[8], n2 = pn[16], n3 = pn[24];
                    float s;
                    {
                        float2 a01 = __bfloat1622float2(*(const __nv_bfloat162*)&c0.x);
                        float2 a23 = __bfloat1622float2(*(const __nv_bfloat162*)&c0.y);
                        s = tanh_fast(a01.x + u0.x) * wA.x;
                        s = fmaf(tanh_fast(a01.y + u0.y), wA.y, s);
                        s = fmaf(tanh_fast(a23.x + u0.z), wA.z, s);
                        s = fmaf(tanh_fast(a23.y + u0.w), wA.w, s);
                    }
                    {
                        float2 a01 = __bfloat1622float2(*(const __nv_bfloat162*)&c1.x);
                        float2 a23 = __bfloat1622float2(*(const __nv_bfloat162*)&c1.y);
                        s = fmaf(tanh_fast(a01.x + u1.x), wB.x, s);
                        s = fmaf(tanh_fast(a01.y + u1.y), wB.y, s);
                        s = fmaf(tanh_fast(a23.x + u1.z), wB.z, s);
                        s = fmaf(tanh_fast(a23.y + u1.w), wB.w, s);
                    }
                    {
                        float2 a01 = __bfloat1622float2(*(const __nv_bfloat162*)&c2.x);
                        float2 a23 = __bfloat1622float2(*(const __nv_bfloat162*)&c2.y);
                        s = fmaf(tanh_fast(a01.x + u2.x), wC.x, s);
                        s = fmaf(tanh_fast(a01.y + u2.y), wC.y, s);
                        s = fmaf(tanh_fast(a23.x + u2.z), wC.z, s);
                        s = fmaf(tanh_fast(a23.y + u2.w), wC.w, s);
                    }
                    {
                        float2 a01 = __bfloat1622float2(*(const __nv_bfloat162*)&c3.x);
                        float2 a23 = __bfloat1622float2(*(const __nv_bfloat162*)&c3.y);
                        s = fmaf(tanh_fast(a01.x + u3.x), wD.x, s);
                        s = fmaf(tanh_fast(a01.y + u3.y), wD.y, s);
                        s = fmaf(tanh_fast(a23.x + u3.z), wD.z, s);
                        s = fmaf(tanh_fast(a23.y + u3.w), wD.w, s);
                    }
                    v[i] = s;
                    c0 = n0; c1 = n1; c2 = n2; c3 = n3;
                }
                bool h1 = l & 1, h2 = l & 2, h4 = l & 4;
                float s0 = h1 ? v[0] : v[1];
                float a0 = (h1 ? v[1] : v[0]) + __shfl_xor_sync(0xffffffffu, s0, 1);
                float s1 = h1 ? v[2] : v[3];
                float a1 = (h1 ? v[3] : v[2]) + __shfl_xor_sync(0xffffffffu, s1, 1);
                float s2 = h1 ? v[4] : v[5];
                float a2 = (h1 ? v[5] : v[4]) + __shfl_xor_sync(0xffffffffu, s2, 1);
                float s3 = h1 ? v[6] : v[7];
                float a3 = (h1 ? v[7] : v[6]) + __shfl_xor_sync(0xffffffffu, s3, 1);
                float t0 = h2 ? a0 : a1;
                float bb0 = (h2 ? a1 : a0) + __shfl_xor_sync(0xffffffffu, t0, 2);
                float t1 = h2 ? a2 : a3;
                float bb1 = (h2 ? a3 : a2) + __shfl_xor_sync(0xffffffffu, t1, 2);
                float t2 = h4 ? bb0 : bb1;
                float ev = (h4 ? bb1 : bb0) + __shfl_xor_sync(0xffffffffu, t2, 4);
                ee[p] = ev + b2;
            }
            float e0 = ee[0], e1 = ee[1];
            float mx = fmaxf(e0, e1);
            #pragma unroll
            for (int o = 16; o > 0; o >>= 1)
                mx = fmaxf(mx, __shfl_xor_sync(0xffffffffu, mx, o));
            float x0 = __expf(e0 - mx), x1 = __expf(e1 - mx);
            float sm = x0 + x1;
            #pragma unroll
            for (int o = 16; o > 0; o >>= 1)
                sm += __shfl_xor_sync(0xffffffffu, sm, o);
            float inv = 1.0f / sm;
            const float* Xr = X + ((size_t)(b0 + w) * TT + t) * NN;
            sXT[w * 64 + l]      = x0 * inv * Xr[l];
            sXT[w * 64 + l + 32] = x1 * inv * Xr[l + 32];
        }
        __syncthreads();

        // ---- (d) gates for batches mb..mb+3 at gate-quad q
        //      (bf16 weights, f32x2 accumulate, one-iter prefetch)
        ull aL0 = bLo, aH0 = bHi, aL1 = bLo, aH1 = bHi;
        ull aL2 = bLo, aH2 = bHi, aL3 = bLo, aH3 = bHi;
        {
            const float4* h40 = (const float4*)(hc + (mb + 0) * HCP);
            const float4* h41 = (const float4*)(hc + (mb + 1) * HCP);
            const float4* h42 = (const float4*)(hc + (mb + 2) * HCP);
            const float4* h43 = (const float4*)(hc + (mb + 3) * HCP);
            const uint2* Wh = g_WhhB + q;
            uint2 wq0 = Wh[0], wq1 = Wh[128], wq2 = Wh[256], wq3 = Wh[384];
            #pragma unroll 4
            for (int j4 = 0; j4 < 32; ++j4) {
                int nj = ((j4 + 1) & 31) * 4;
                uint2 f0 = Wh[(size_t)(nj + 0) * 128];
                uint2 f1 = Wh[(size_t)(nj + 1) * 128];
                uint2 f2 = Wh[(size_t)(nj + 2) * 128];
                uint2 f3 = Wh[(size_t)(nj + 3) * 128];
                float4 v0 = h40[j4], v1 = h41[j4], v2 = h42[j4], v3 = h43[j4];
                ull p0, p1, p2, p3;
                PKS(x); GSTEP(wq0.x, wq0.y);
                PKS(y); GSTEP(wq1.x, wq1.y);
                PKS(z); GSTEP(wq2.x, wq2.y);
                PKS(w); GSTEP(wq3.x, wq3.y);
                wq0 = f0; wq1 = f1; wq2 = f2; wq3 = f3;
            }
            const float4* x40 = (const float4*)(sXT + (mb + 0) * 64);
            const float4* x41 = (const float4*)(sXT + (mb + 1) * 64);
            const float4* x42 = (const float4*)(sXT + (mb + 2) * 64);
            const float4* x43 = (const float4*)(sXT + (mb + 3) * 64);
            const uint2* Wi = g_WihB + q;
            wq0 = Wi[0]; wq1 = Wi[128]; wq2 = Wi[256]; wq3 = Wi[384];
            #pragma unroll 4
            for (int n4 = 0; n4 < 16; ++n4) {
                int nj = ((n4 + 1) & 15) * 4;
                uint2 f0 = Wi[(size_t)(nj + 0) * 128];
                uint2 f1 = Wi[(size_t)(nj + 1) * 128];
                uint2 f2 = Wi[(size_t)(nj + 2) * 128];
                uint2 f3 = Wi[(size_t)(nj + 3) * 128];
                float4 v0 = x40[n4], v1 = x41[n4], v2 = x42[n4], v3 = x43[n4];
                ull p0, p1, p2, p3;
                PKS(x); GSTEP(wq0.x, wq0.y);
                PKS(y); GSTEP(wq1.x, wq1.y);
                PKS(z); GSTEP(wq2.x, wq2.y);
                PKS(w); GSTEP(wq3.x, wq3.y);
                wq0 = f0; wq1 = f1; wq2 = f2; wq3 = f3;
            }
        }

        // ---- (e) LSTM pointwise update -> double-buffered state + output
        #pragma unroll
        for (int mm = 0; mm < 4; ++mm) {
            if (mb + mm < cnt) {
                ull aL = (mm == 0) ? aL0 : (mm == 1) ? aL1 : (mm == 2) ? aL2 : aL3;
                ull aH = (mm == 0) ? aH0 : (mm == 1) ? aH1 : (mm == 2) ? aH2 : aH3;
                float2 gif = up2(aL);
                float2 ggo = up2(aH);
                float iv = sigmoid_f(gif.x);
                float fv = sigmoid_f(gif.y);
                float gv = tanhf(ggo.x);
                float ov = sigmoid_f(ggo.y);
                float cold = hc[(mb + mm) * HCP + 128 + q];
                float c2 = fv * cold + iv * gv;
                float hn = ov * tanhf(c2);
                hcn[(mb + mm) * HCP + q]       = hn;
                hcn[(mb + mm) * HCP + 128 + q] = c2;
                out[((size_t)(b0 + mb + mm) * TT + t) * HH + q] = hn;
            }
        }
        __syncthreads();
    }
}

// ---------------- launch ------------------------------------------------------
extern "C" void kernel_launch(void* const* d_in, const int* in_sizes, int n_in,
                              void* d_out, int out_size) {
    const float* X       = (const float*)d_in[0];
    const float* W_attn1 = (const float*)d_in[1];
    const float* b_attn1 = (const float*)d_in[2];
    const float* w_attn2 = (const float*)d_in[3];
    const float* b_attn2 = (const float*)d_in[4];
    const float* W_ih    = (const float*)d_in[5];
    const float* W_hh    = (const float*)d_in[6];
    const float* b_ih    = (const float*)d_in[7];
    const float* b_hh    = (const float*)d_in[8];
    float* out = (float*)d_out;

    cudaFuncSetAttribute(rnn_kernel, cudaFuncAttributeMaxDynamicSharedMemorySize,
                         SMEM_FLOATS * (int)sizeof(float));

    prep_kernel<<<64, 256>>>(W_attn1, W_ih, W_hh, b_ih, b_hh);
    prex_kernel<<<BB, 256>>>(X, b_attn1);
    dummy_kernel<<<1, 32>>>();   // aligns ncu -s 5 -c 1 onto rnn_kernel
    rnn_kernel<<<GRID, THR, SMEM_FLOATS * sizeof(float)>>>(X, w_attn2, b_attn2, out);
}

// round 17
// speedup vs baseline: 1.1960x; 1.0317x over previous
#include <cuda_runtime.h>
#include <cuda_bf16.h>

#define BB 2048
#define TT 128
#define NN 64
#define HH 128
#define THR 256   // threads per CTA (8 warps)
#define GRID 296  // 2 CTAs per SM
#define NFULL 272 // CTAs with 7 batches; remaining 24 have 6
#define HCP 264   // padded hc row stride (floats)

typedef unsigned long long ull;

// ---------------- device scratch (allocation-free: __device__ globals) -------
__device__ __align__(16) __nv_bfloat16 g_prex_bf[(size_t)BB * NN * HH]; // [b][n][kq]
__device__ __align__(16) uint2 g_WatB[256 * 32];   // [j][kq] bf16x4 attention wts
__device__ __align__(16) float g_W1xT[TT * HH];    // [t][k]
__device__ __align__(16) uint2 g_WhhB[HH * 128];   // [j][q] bf16x2 pair {(i,f),(g,o)}
__device__ __align__(16) uint2 g_WihB[NN * 128];   // [n][q]
__device__ __align__(16) float g_bG[512];          // [q*4+gate] fp32

__device__ __forceinline__ ull pk2(float a, float b) {
    ull r; asm("mov.b64 %0,{%1,%2};" : "=l"(r) : "f"(a), "f"(b)); return r;
}
__device__ __forceinline__ void fma2(ull& d, ull a, ull b) {
    asm("fma.rn.f32x2 %0, %1, %2, %0;" : "+l"(d) : "l"(a), "l"(b));
}
__device__ __forceinline__ ull add2(ull a, ull b) {
    ull r; asm("add.rn.f32x2 %0, %1, %2;" : "=l"(r) : "l"(a), "l"(b)); return r;
}
__device__ __forceinline__ float2 up2(ull v) {
    float2 r; asm("mov.b64 {%0,%1},%2;" : "=f"(r.x), "=f"(r.y) : "l"(v)); return r;
}
// bf16x2 word -> packed f32x2 (low bf16 -> low f32)
__device__ __forceinline__ ull expw(unsigned wd) {
    unsigned lo = wd << 16, hi = wd & 0xFFFF0000u;
    ull r; asm("mov.b64 %0,{%1,%2};" : "=l"(r) : "r"(lo), "r"(hi)); return r;
}
__device__ __forceinline__ float tanh_fast(float x) {
    float y; asm("tanh.approx.f32 %0, %1;" : "=f"(y) : "f"(x)); return y;
}
__device__ __forceinline__ float sigmoid_f(float x) {
    return 1.0f / (1.0f + __expf(-x));
}
__device__ __forceinline__ void fma4(float4& a, float s, const float4 w) {
    a.x = fmaf(s, w.x, a.x); a.y = fmaf(s, w.y, a.y);
    a.z = fmaf(s, w.z, a.z); a.w = fmaf(s, w.w, a.w);
}
__device__ __forceinline__ unsigned b2u(__nv_bfloat162 v) {
    unsigned r; *(__nv_bfloat162*)&r = v; return r;
}

// ---------------- kernel 0: weight layout prep --------------------------------
__global__ void prep_kernel(const float* __restrict__ W_attn1,
                            const float* __restrict__ W_ih,
                            const float* __restrict__ W_hh,
                            const float* __restrict__ b_ih,
                            const float* __restrict__ b_hh)
{
    int tid = blockIdx.x * blockDim.x + threadIdx.x;
    int nt  = gridDim.x * blockDim.x;
    for (int i = tid; i < 256 * 32; i += nt) {
        int j = i >> 5, kq = i & 31, k = kq * 4;
        uint2 v;
        v.x = b2u(__floats2bfloat162_rn(W_attn1[(k+0)*384 + j], W_attn1[(k+1)*384 + j]));
        v.y = b2u(__floats2bfloat162_rn(W_attn1[(k+2)*384 + j], W_attn1[(k+3)*384 + j]));
        g_WatB[i] = v;
    }
    for (int i = tid; i < TT * HH; i += nt) {
        int t = i >> 7, k = i & 127;
        g_W1xT[i] = W_attn1[k * 384 + 256 + t];
    }
    for (int i = tid; i < HH * 128; i += nt) {
        int j = i >> 7, q = i & 127;
        uint2 v;
        v.x = b2u(__floats2bfloat162_rn(W_hh[(0*HH+q)*HH + j], W_hh[(1*HH+q)*HH + j]));
        v.y = b2u(__floats2bfloat162_rn(W_hh[(2*HH+q)*HH + j], W_hh[(3*HH+q)*HH + j]));
        g_WhhB[i] = v;
    }
    for (int i = tid; i < NN * 128; i += nt) {
        int n = i >> 7, q = i & 127;
        uint2 v;
        v.x = b2u(__floats2bfloat162_rn(W_ih[(0*HH+q)*NN + n], W_ih[(1*HH+q)*NN + n]));
        v.y = b2u(__floats2bfloat162_rn(W_ih[(2*HH+q)*NN + n], W_ih[(3*HH+q)*NN + n]));
        g_WihB[i] = v;
    }
    for (int i = tid; i < 512; i += nt) {
        int q = i >> 2, g = i & 3;
        g_bG[i] = b_ih[g * HH + q] + b_hh[g * HH + q];
    }
}

// ---------------- kernel 1: pre_x (bf16 out) ----------------------------------
__global__ __launch_bounds__(256) void prex_kernel(const float* __restrict__ X,
                                                   const float* __restrict__ b_attn1)
{
    __shared__ float sX[TT * NN];
    int b = blockIdx.x;
    int tid = threadIdx.x;
    const float* Xb = X + (size_t)b * TT * NN;
    for (int i = tid; i < TT * NN; i += 256) sX[i] = Xb[i];
    __syncthreads();

    const float4* W4  = (const float4*)g_W1xT;
    const float4* b14 = (const float4*)b_attn1;
    uint2* out2 = (uint2*)(g_prex_bf + (size_t)b * NN * HH);

    for (int qi = tid; qi < NN * 32; qi += 256) {
        int n = qi >> 5, kq = qi & 31;
        float4 acc = b14[kq];
        #pragma unroll 4
        for (int t = 0; t < TT; ++t) {
            float x = sX[t * NN + n];
            fma4(acc, x, W4[t * 32 + kq]);
        }
        uint2 st;
        st.x = b2u(__floats2bfloat162_rn(acc.x, acc.y));
        st.y = b2u(__floats2bfloat162_rn(acc.z, acc.w));
        out2[n * 32 + kq] = st;
    }
}

// dummy: shifts launch numbering so ncu (-s 5 -c 1) lands on rnn_kernel
__global__ void dummy_kernel() {}

// ---------------- kernel 2: the recurrence ------------------------------------
// smem (floats): sWb 16384 | hcA 2112 | hcB 2112 | hdup 4096 | sUp 3584 | sXT 512
#define SMEM_FLOATS (16384 + 2112 + 2112 + 4096 + 3584 + 512)

#define PKS(c) p0 = pk2(v0.c, v0.c); p1 = pk2(v1.c, v1.c); \
               p2 = pk2(v2.c, v2.c); p3 = pk2(v3.c, v3.c)
#define GSTEP(wl, wh) { ull wx = expw(wl), wy = expw(wh); \
    fma2(aL0, p0, wx); fma2(aH0, p0, wy); fma2(aL1, p1, wx); fma2(aH1, p1, wy); \
    fma2(aL2, p2, wx); fma2(aH2, p2, wy); fma2(aL3, p3, wx); fma2(aH3, p3, wy); }

__global__ __launch_bounds__(THR, 2) void rnn_kernel(
    const float* __restrict__ X,
    const float* __restrict__ w_attn2,
    const float* __restrict__ b_attn2,
    float* __restrict__ out)
{
    extern __shared__ float smem[];
    uint2* sWb  = (uint2*)smem;            // [256 j][32 kq]
    float* hcA  = smem + 16384;
    float* hcB  = hcA + 2112;
    ull*   hdup = (ull*)(smem + 20608);    // [256 j][8 b] (v,v) pairs; j>=128: c
    ull*   sUp  = (ull*)(smem + 24704);    // [4 jq][7 b][64] u partials
    float* sXT  = smem + 28288;            // [8 b][64 n]

    int tid = threadIdx.x;
    int l = tid & 31;
    int w = tid >> 5;                      // 0..7
    int cta = blockIdx.x;
    int cnt  = (cta < NFULL) ? 7 : 6;
    size_t b0 = (cta < NFULL) ? (size_t)cta * 7
                              : (size_t)(NFULL * 7 + (cta - NFULL) * 6);

    {   // stage bf16 attention weights into smem (once)
        const uint4* src = (const uint4*)g_WatB;
        uint4* dst = (uint4*)sWb;
        #pragma unroll 4
        for (int i = tid; i < 4096; i += THR) dst[i] = src[i];
    }
    for (int i = tid; i < 4224; i += THR) hcA[i] = 0.0f;   // zero both hc buffers
    for (int i = tid; i < 2048; i += THR) hdup[i] = 0ull;  // zero dup state
    for (int i = tid; i < 512; i += THR) sXT[i] = 0.0f;

    float b2 = b_attn2[0];

    // (a) mapping: thread = (batch-group tid>>7) x (j-quarter) x (k-quad)
    int bgA  = tid >> 7;                   // 0: b0..3, 1: b4..7(pad)
    int jqA  = (tid >> 5) & 3;             // j in [jqA*64, jqA*64+64)
    int kq2  = tid & 31;                   // k-quad 0..31
    int bbA  = bgA * 4;

    // (d) mapping: q in 0..127, 2 groups of 4 batches
    int q = tid & 127, grp = tid >> 7, mb = grp * 4;
    float4 bgq = ((const float4*)g_bG)[q];
    ull bLo = pk2(bgq.x, bgq.y), bHi = pk2(bgq.z, bgq.w);

    int mw = (w < cnt) ? w : 0;
    const uint2* prb = (const uint2*)g_prex_bf + (size_t)(b0 + mw) * 2048;

    __syncthreads();

    for (int t = 0; t < TT; ++t) {
        float* hc  = (t & 1) ? hcB : hcA;
        float* hcn = (t & 1) ? hcA : hcB;

        // ---- (a) u partials: 64 j for 4 batches; weight expanded ONCE per 4 fma2
        {
            const uint2* Wj = sWb + (size_t)(jqA * 64) * 32 + kq2;
            const ull* hj = hdup + (size_t)(jqA * 64) * 8 + bbA;
            ull aL0 = 0, aH0 = 0, aL1 = 0, aH1 = 0;
            ull aL2 = 0, aH2 = 0, aL3 = 0, aH3 = 0;
            #pragma unroll 4
            for (int jj = 0; jj < 64; ++jj) {
                uint2 wd = Wj[jj * 32];
                ull w0 = expw(wd.x), w1 = expw(wd.y);
                ulonglong2 h01 = *(const ulonglong2*)(hj + jj * 8);
                ulonglong2 h23 = *(const ulonglong2*)(hj + jj * 8 + 2);
                fma2(aL0, h01.x, w0); fma2(aH0, h01.x, w1);
                fma2(aL1, h01.y, w0); fma2(aH1, h01.y, w1);
                fma2(aL2, h23.x, w0); fma2(aH2, h23.x, w1);
                fma2(aL3, h23.y, w0); fma2(aH3, h23.y, w1);
            }
            ull* su = sUp + (size_t)(jqA * 7 + bbA) * 64 + kq2 * 2;
            su[0] = aL0; su[1] = aH0;
            su += 64; su[0] = aL1; su[1] = aH1;
            su += 64; su[0] = aL2; su[1] = aH2;
            if (bbA + 3 < 7) { su += 64; su[0] = aL3; su[1] = aH3; }
        }
        __syncthreads();

        // ---- (b)+(c): assemble u from 4 jq partials, tanh/scores/softmax/x~
        if (w < cnt) {
            int kq = l & 7;
            float4 u0, u1, u2, u3;
            {
                const ulonglong2* s0 = (const ulonglong2*)(sUp + (size_t)(0 * 7 + w) * 64);
                const ulonglong2* s1 = (const ulonglong2*)(sUp + (size_t)(1 * 7 + w) * 64);
                const ulonglong2* s2 = (const ulonglong2*)(sUp + (size_t)(2 * 7 + w) * 64);
                const ulonglong2* s3 = (const ulonglong2*)(sUp + (size_t)(3 * 7 + w) * 64);
                #pragma unroll
                for (int qi = 0; qi < 4; ++qi) {
                    int K = kq + qi * 8;
                    ulonglong2 a = s0[K], bq_ = s1[K], c = s2[K], d = s3[K];
                    ull lo = add2(add2(a.x, bq_.x), add2(c.x, d.x));
                    ull hi = add2(add2(a.y, bq_.y), add2(c.y, d.y));
                    float2 flo = up2(lo), fhi = up2(hi);
                    float4 uq = make_float4(flo.x, flo.y, fhi.x, fhi.y);
                    if (qi == 0) u0 = uq; else if (qi == 1) u1 = uq;
                    else if (qi == 2) u2 = uq; else u3 = uq;
                }
            }
            const float4* w24 = (const float4*)w_attn2;
            float4 wA = w24[kq], wB = w24[kq + 8], wC = w24[kq + 16], wD = w24[kq + 24];
            float ee[2];
            #pragma unroll
            for (int p = 0; p < 2; ++p) {
                int nb = p * 32 + (l & 24);
                const uint2* pp = prb + (size_t)nb * 32 + kq;
                uint2 c0 = pp[0], c1 = pp[8], c2 = pp[16], c3 = pp[24];
                float v[8];
                #pragma unroll
                for (int i = 0; i < 8; ++i) {
                    const uint2* pn = prb + (size_t)(nb + ((i + 1) & 7)) * 32 + kq;
                    uint2 n0 = pn[0], n1 = pn[8], n2 = pn[16], n3 = pn[24];
                    float s;
                    {
                        float2 a01 = __bfloat1622float2(*(const __nv_bfloat162*)&c0.x);
                        float2 a23 = __bfloat1622float2(*(const __nv_bfloat162*)&c0.y);
                        s = tanh_fast(a01.x + u0.x) * wA.x;
                        s = fmaf(tanh_fast(a01.y + u0.y), wA.y, s);
                        s = fmaf(tanh_fast(a23.x + u0.z), wA.z, s);
                        s = fmaf(tanh_fast(a23.y + u0.w), wA.w, s);
                    }
                    {
                        float2 a01 = __bfloat1622float2(*(const __nv_bfloat162*)&c1.x);
                        float2 a23 = __bfloat1622float2(*(const __nv_bfloat162*)&c1.y);
                        s = fmaf(tanh_fast(a01.x + u1.x), wB.x, s);
                        s = fmaf(tanh_fast(a01.y + u1.y), wB.y, s);
                        s = fmaf(tanh_fast(a23.x + u1.z), wB.z, s);
                        s = fmaf(tanh_fast(a23.y + u1.w), wB.w, s);
                    }
                    {
                        float2 a01 = __bfloat1622float2(*(const __nv_bfloat162*)&c2.x);
                        float2 a23 = __bfloat1622float2(*(const __nv_bfloat162*)&c2.y);
                        s = fmaf(tanh_fast(a01.x + u2.x), wC.x, s);
                        s = fmaf(tanh_fast(a01.y + u2.y), wC.y, s);
                        s = fmaf(tanh_fast(a23.x + u2.z), wC.z, s);
                        s = fmaf(tanh_fast(a23.y + u2.w), wC.w, s);
                    }
                    {
                        float2 a01 = __bfloat1622float2(*(const __nv_bfloat162*)&c3.x);
                        float2 a23 = __bfloat1622float2(*(const __nv_bfloat162*)&c3.y);
                        s = fmaf(tanh_fast(a01.x + u3.x), wD.x, s);
                        s = fmaf(tanh_fast(a01.y + u3.y), wD.y, s);
                        s = fmaf(tanh_fast(a23.x + u3.z), wD.z, s);
                        s = fmaf(tanh_fast(a23.y + u3.w), wD.w, s);
                    }
                    v[i] = s;
                    c0 = n0; c1 = n1; c2 = n2; c3 = n3;
                }
                bool h1 = l & 1, h2 = l & 2, h4 = l & 4;
                float s0 = h1 ? v[0] : v[1];
                float a0 = (h1 ? v[1] : v[0]) + __shfl_xor_sync(0xffffffffu, s0, 1);
                float s1 = h1 ? v[2] : v[3];
                float a1 = (h1 ? v[3] : v[2]) + __shfl_xor_sync(0xffffffffu, s1, 1);
                float s2 = h1 ? v[4] : v[5];
                float a2 = (h1 ? v[5] : v[4]) + __shfl_xor_sync(0xffffffffu, s2, 1);
                float s3 = h1 ? v[6] : v[7];
                float a3 = (h1 ? v[7] : v[6]) + __shfl_xor_sync(0xffffffffu, s3, 1);
                float t0 = h2 ? a0 : a1;
                float bb0 = (h2 ? a1 : a0) + __shfl_xor_sync(0xffffffffu, t0, 2);
                float t1 = h2 ? a2 : a3;
                float bb1 = (h2 ? a3 : a2) + __shfl_xor_sync(0xffffffffu, t1, 2);
                float t2 = h4 ? bb0 : bb1;
                float ev = (h4 ? bb1 : bb0) + __shfl_xor_sync(0xffffffffu, t2, 4);
                ee[p] = ev + b2;
            }
            float e0 = ee[0], e1 = ee[1];
            float mx = fmaxf(e0, e1);
            #pragma unroll
            for (int o = 16; o > 0; o >>= 1)
                mx = fmaxf(mx, __shfl_xor_sync(0xffffffffu, mx, o));
            float x0 = __expf(e0 - mx), x1 = __expf(e1 - mx);
            float sm = x0 + x1;
            #pragma unroll
            for (int o = 16; o > 0; o >>= 1)
                sm += __shfl_xor_sync(0xffffffffu, sm, o);
            float inv = 1.0f / sm;
            const float* Xr = X + ((size_t)(b0 + w) * TT + t) * NN;
            sXT[w * 64 + l]      = x0 * inv * Xr[l];
            sXT[w * 64 + l + 32] = x1 * inv * Xr[l + 32];
        }
        __syncthreads();

        // ---- (d) gates for batches mb..mb+3 at gate-quad q
        ull aL0 = bLo, aH0 = bHi, aL1 = bLo, aH1 = bHi;
        ull aL2 = bLo, aH2 = bHi, aL3 = bLo, aH3 = bHi;
        {
            const float4* h40 = (const float4*)(hc + (mb + 0) * HCP);
            const float4* h41 = (const float4*)(hc + (mb + 1) * HCP);
            const float4* h42 = (const float4*)(hc + (mb + 2) * HCP);
            const float4* h43 = (const float4*)(hc + (mb + 3) * HCP);
            const uint2* Wh = g_WhhB + q;
            uint2 wq0 = Wh[0], wq1 = Wh[128], wq2 = Wh[256], wq3 = Wh[384];
            #pragma unroll 4
            for (int j4 = 0; j4 < 32; ++j4) {
                int nj = ((j4 + 1) & 31) * 4;
                uint2 f0 = Wh[(size_t)(nj + 0) * 128];
                uint2 f1 = Wh[(size_t)(nj + 1) * 128];
                uint2 f2 = Wh[(size_t)(nj + 2) * 128];
                uint2 f3 = Wh[(size_t)(nj + 3) * 128];
                float4 v0 = h40[j4], v1 = h41[j4], v2 = h42[j4], v3 = h43[j4];
                ull p0, p1, p2, p3;
                PKS(x); GSTEP(wq0.x, wq0.y);
                PKS(y); GSTEP(wq1.x, wq1.y);
                PKS(z); GSTEP(wq2.x, wq2.y);
                PKS(w); GSTEP(wq3.x, wq3.y);
                wq0 = f0; wq1 = f1; wq2 = f2; wq3 = f3;
            }
            const float4* x40 = (const float4*)(sXT + (mb + 0) * 64);
            const float4* x41 = (const float4*)(sXT + (mb + 1) * 64);
            const float4* x42 = (const float4*)(sXT + (mb + 2) * 64);
            const float4* x43 = (const float4*)(sXT + (mb + 3) * 64);
            const uint2* Wi = g_WihB + q;
            wq0 = Wi[0]; wq1 = Wi[128]; wq2 = Wi[256]; wq3 = Wi[384];
            #pragma unroll 4
            for (int n4 = 0; n4 < 16; ++n4) {
                int nj = ((n4 + 1) & 15) * 4;
                uint2 f0 = Wi[(size_t)(nj + 0) * 128];
                uint2 f1 = Wi[(size_t)(nj + 1) * 128];
                uint2 f2 = Wi[(size_t)(nj + 2) * 128];
                uint2 f3 = Wi[(size_t)(nj + 3) * 128];
                float4 v0 = x40[n4], v1 = x41[n4], v2 = x42[n4], v3 = x43[n4];
                ull p0, p1, p2, p3;
                PKS(x); GSTEP(wq0.x, wq0.y);
                PKS(y); GSTEP(wq1.x, wq1.y);
                PKS(z); GSTEP(wq2.x, wq2.y);
                PKS(w); GSTEP(wq3.x, wq3.y);
                wq0 = f0; wq1 = f1; wq2 = f2; wq3 = f3;
            }
        }

        // ---- (e) LSTM pointwise update -> plain + dup state + output
        #pragma unroll
        for (int mm = 0; mm < 4; ++mm) {
            if (mb + mm < cnt) {
                ull aL = (mm == 0) ? aL0 : (mm == 1) ? aL1 : (mm == 2) ? aL2 : aL3;
                ull aH = (mm == 0) ? aH0 : (mm == 1) ? aH1 : (mm == 2) ? aH2 : aH3;
                float2 gif = up2(aL);
                float2 ggo = up2(aH);
                float iv = sigmoid_f(gif.x);
                float fv = sigmoid_f(gif.y);
                float gv = tanhf(ggo.x);
                float ov = sigmoid_f(ggo.y);
                float cold = hc[(mb + mm) * HCP + 128 + q];
                float c2 = fv * cold + iv * gv;
                float hn = ov * tanhf(c2);
                hcn[(mb + mm) * HCP + q]       = hn;
                hcn[(mb + mm) * HCP + 128 + q] = c2;
                hdup[(size_t)q * 8 + (mb + mm)]         = pk2(hn, hn);
                hdup[(size_t)(128 + q) * 8 + (mb + mm)] = pk2(c2, c2);
                out[((size_t)(b0 + mb + mm) * TT + t) * HH + q] = hn;
            }
        }
        __syncthreads();
    }
}

// ---------------- launch ------------------------------------------------------
extern "C" void kernel_launch(void* const* d_in, const int* in_sizes, int n_in,
                              void* d_out, int out_size) {
    const float* X       = (const float*)d_in[0];
    const float* W_attn1 = (const float*)d_in[1];
    const float* b_attn1 = (const float*)d_in[2];
    const float* w_attn2 = (const float*)d_in[3];
    const float* b_attn2 = (const float*)d_in[4];
    const float* W_ih    = (const float*)d_in[5];
    const float* W_hh    = (const float*)d_in[6];
    const float* b_ih    = (const float*)d_in[7];
    const float* b_hh    = (const float*)d_in[8];
    float* out = (float*)d_out;

    cudaFuncSetAttribute(rnn_kernel, cudaFuncAttributeMaxDynamicSharedMemorySize,
                         SMEM_FLOATS * (int)sizeof(float));

    prep_kernel<<<64, 256>>>(W_attn1, W_ih, W_hh, b_ih, b_hh);
    prex_kernel<<<BB, 256>>>(X, b_attn1);
    dummy_kernel<<<1, 32>>>();   // aligns ncu -s 5 -c 1 onto rnn_kernel
    rnn_kernel<<<GRID, THR, SMEM_FLOATS * sizeof(float)>>>(X, w_attn2, b_attn2, out);
}